// round 9
// baseline (speedup 1.0000x reference)
#include <cuda_runtime.h>

#define B_ 64
#define S_ 8192
#define E_ 32
#define H_ 64
// ---- pass A tiling (unchanged from R8) ----
#define T_ 128
#define TILES_ (S_ / T_)       // 64
#define TPA_ 4
#define NBA_ (TILES_ / TPA_)   // 16
#define XP_ 132
// ---- pass B tiling (new) ----
#define TB_TOK 256
#define TB_TILES (S_ / TB_TOK) // 32
#define TPB_ 8                 // tiles per pass-B block -> grid (4, 64)
#define HS_STR 260             // hs row stride (floats)
// dynamic smem float offsets for pass B
#define W1T_OFF 0
#define W2T_OFF 2048
#define HS_OFF  4096
#define B1_OFF  (HS_OFF + H_ * HS_STR)   // 20736
#define B2_OFF  (B1_OFF + 64)
#define RSQ_OFF (B2_OFF + 32)
#define SMB_FLOATS (RSQ_OFF + 32)        // 20864 -> 83456 B

typedef unsigned long long u64;

// Scratch: q in [b][tile128][f][128] layout + per-block sumsq partials.
__device__ __align__(16) static float g_q[(size_t)B_ * S_ * E_];
__device__ static float g_part[B_ * NBA_ * E_];

__device__ __forceinline__ u64 pack2(float lo, float hi) {
    u64 r; asm("mov.b64 %0, {%1,%2};" : "=l"(r) : "f"(lo), "f"(hi)); return r;
}
__device__ __forceinline__ float2 unpack2(u64 v) {
    float2 f; asm("mov.b64 {%0,%1}, %2;" : "=f"(f.x), "=f"(f.y) : "l"(v)); return f;
}
__device__ __forceinline__ u64 ffma2(u64 a, u64 b, u64 c) {
    u64 d; asm("fma.rn.f32x2 %0, %1, %2, %3;" : "=l"(d) : "l"(a), "l"(b), "l"(c));
    return d;
}
__device__ __forceinline__ float silu_f(float v) {
    return v * __fdividef(1.0f, 1.0f + __expf(-v));  // ~1e-7 rel err; budget 1e-3
}

// ---------------- Pass A: q = silu(x @ Qw^T); per-block sumsq partials (R8) -----------
__global__ __launch_bounds__(256) void k_passA(const float* __restrict__ x,
                                               const float* __restrict__ Qw) {
    const int b = blockIdx.y, bx = blockIdx.x;
    const int tid = threadIdx.x, lane = tid & 31, wy = tid >> 5;
    __shared__ __align__(16) float Qt[E_ * E_];   // [e][f]
    __shared__ __align__(16) float xs[E_ * XP_];  // [e][t], padded

    {   // conflict-free transposed fill: lane carries f
        int f = tid & 31, eg = tid >> 5;
        for (int e = eg; e < E_; e += 8) Qt[e * E_ + f] = Qw[f * E_ + e];
    }

    const int t0 = lane * 4, f0 = wy * 4;
    float ss[4] = {0.f, 0.f, 0.f, 0.f};

    for (int tt = 0; tt < TPA_; ++tt) {
        const int tile = bx * TPA_ + tt;
        __syncthreads();
        const float4* xg = reinterpret_cast<const float4*>(
            x + ((size_t)b * S_ + tile * T_) * E_);
        for (int i = tid; i < T_ * E_ / 4; i += 256) {
            float4 v = xg[i];
            int t = i >> 3, e = (i & 7) * 4;
            xs[(e + 0) * XP_ + t] = v.x;
            xs[(e + 1) * XP_ + t] = v.y;
            xs[(e + 2) * XP_ + t] = v.z;
            xs[(e + 3) * XP_ + t] = v.w;
        }
        __syncthreads();

        u64 acc[2][4];
#pragma unroll
        for (int fp = 0; fp < 2; ++fp)
#pragma unroll
            for (int t = 0; t < 4; ++t) acc[fp][t] = 0ull;

#pragma unroll
        for (int e = 0; e < E_; ++e) {
            float4 q = *reinterpret_cast<const float4*>(&xs[e * XP_ + t0]);
            u64 qb0 = pack2(q.x, q.x), qb1 = pack2(q.y, q.y);
            u64 qb2 = pack2(q.z, q.z), qb3 = pack2(q.w, q.w);
            ulonglong2 w = *reinterpret_cast<const ulonglong2*>(&Qt[e * E_ + f0]);
            acc[0][0] = ffma2(w.x, qb0, acc[0][0]);
            acc[0][1] = ffma2(w.x, qb1, acc[0][1]);
            acc[0][2] = ffma2(w.x, qb2, acc[0][2]);
            acc[0][3] = ffma2(w.x, qb3, acc[0][3]);
            acc[1][0] = ffma2(w.y, qb0, acc[1][0]);
            acc[1][1] = ffma2(w.y, qb1, acc[1][1]);
            acc[1][2] = ffma2(w.y, qb2, acc[1][2]);
            acc[1][3] = ffma2(w.y, qb3, acc[1][3]);
        }

        float* qb = g_q + (((size_t)b * TILES_ + tile) * E_ + f0) * T_ + t0;
#pragma unroll
        for (int fp = 0; fp < 2; ++fp) {
            float2 a0 = unpack2(acc[fp][0]), a1 = unpack2(acc[fp][1]);
            float2 a2 = unpack2(acc[fp][2]), a3 = unpack2(acc[fp][3]);
            float l0 = silu_f(a0.x), l1 = silu_f(a1.x), l2 = silu_f(a2.x), l3 = silu_f(a3.x);
            float h0 = silu_f(a0.y), h1 = silu_f(a1.y), h2 = silu_f(a2.y), h3 = silu_f(a3.y);
            *reinterpret_cast<float4*>(qb + (2 * fp + 0) * T_) = make_float4(l0, l1, l2, l3);
            *reinterpret_cast<float4*>(qb + (2 * fp + 1) * T_) = make_float4(h0, h1, h2, h3);
            ss[2 * fp + 0] += l0 * l0 + l1 * l1 + l2 * l2 + l3 * l3;
            ss[2 * fp + 1] += h0 * h0 + h1 * h1 + h2 * h2 + h3 * h3;
        }
    }

#pragma unroll
    for (int i = 0; i < 4; ++i) {
#pragma unroll
        for (int o = 16; o > 0; o >>= 1) ss[i] += __shfl_xor_sync(0xffffffffu, ss[i], o);
    }
    if (lane == 0) {
#pragma unroll
        for (int i = 0; i < 4; ++i) g_part[(b * NBA_ + bx) * E_ + f0 + i] = ss[i];
    }
}

// ---------------- Pass B: T=256 tiles, 8tx8j GEMM1 / 8tx4e GEMM2 ----------------
__global__ __launch_bounds__(256, 2) void k_passB(const float* __restrict__ W1,
                                                  const float* __restrict__ b1,
                                                  const float* __restrict__ W2,
                                                  const float* __restrict__ b2,
                                                  float* __restrict__ out) {
    extern __shared__ __align__(16) float sm[];
    float* W1t = sm + W1T_OFF;   // [e][j] scaled by 1/norm[e]
    float* W2t = sm + W2T_OFF;   // [j][e]
    float* hs  = sm + HS_OFF;    // [j][HS_STR]
    float* b1s = sm + B1_OFF;
    float* b2s = sm + B2_OFF;
    float* rsq = sm + RSQ_OFF;

    const int b = blockIdx.y, bx = blockIdx.x, tid = threadIdx.x;

    if (tid < E_) {
        float s = 0.f;
#pragma unroll
        for (int k = 0; k < NBA_; ++k) s += g_part[(b * NBA_ + k) * E_ + tid];
        rsq[tid] = 1.0f / fmaxf(sqrtf(s), 1e-12f);
        b2s[tid] = b2[b * E_ + tid];
    }
    if (tid < H_) b1s[tid] = b1[b * H_ + tid];
    __syncthreads();

    const size_t wbase = (size_t)b * H_ * E_;
    {   // conflict-free transposed weight fills (lane carries bank-varying index)
        int j = tid & 63, eg = tid >> 6;
        for (int e = eg; e < E_; e += 4)
            W1t[e * H_ + j] = W1[wbase + j * E_ + e] * rsq[e];
    }
    {
        int e = tid & 31, jg = tid >> 5;
        for (int j = jg; j < H_; j += 8)
            W2t[j * E_ + e] = W2[wbase + e * H_ + j];
    }
    __syncthreads();

    const float* qrow = g_q + (size_t)b * TILES_ * E_ * T_;  // [tile128][e][128]

    for (int tt = 0; tt < TPB_; ++tt) {
        const int tileB = bx * TPB_ + tt;

        // ---- GEMM1: warp owns 8 j; lane owns 8 tokens (coalesced q LDG) ----
        {
            const int j0 = (tid >> 5) * 8;
            const int t0 = (tid & 31) * 8;
            const int s0 = tileB * TB_TOK + t0;
            const float* qbase = qrow + ((size_t)(s0 >> 7) * E_) * T_ + (s0 & 127);

            u64 hacc[4][8];
#pragma unroll
            for (int jp = 0; jp < 4; ++jp) {
                u64 bp = *reinterpret_cast<const u64*>(&b1s[j0 + 2 * jp]);
#pragma unroll
                for (int t = 0; t < 8; ++t) hacc[jp][t] = bp;
            }
#pragma unroll 4
            for (int e = 0; e < E_; ++e) {
                const float4* qp = reinterpret_cast<const float4*>(qbase + (size_t)e * T_);
                float4 qa = qp[0], qc = qp[1];
                u64 qq[8] = {pack2(qa.x, qa.x), pack2(qa.y, qa.y),
                             pack2(qa.z, qa.z), pack2(qa.w, qa.w),
                             pack2(qc.x, qc.x), pack2(qc.y, qc.y),
                             pack2(qc.z, qc.z), pack2(qc.w, qc.w)};
                ulonglong2 wa = *reinterpret_cast<const ulonglong2*>(&W1t[e * H_ + j0]);
                ulonglong2 wb = *reinterpret_cast<const ulonglong2*>(&W1t[e * H_ + j0 + 4]);
                u64 wv[4] = {wa.x, wa.y, wb.x, wb.y};
#pragma unroll
                for (int jp = 0; jp < 4; ++jp)
#pragma unroll
                    for (int t = 0; t < 8; ++t)
                        hacc[jp][t] = ffma2(wv[jp], qq[t], hacc[jp][t]);
            }
#pragma unroll
            for (int jp = 0; jp < 4; ++jp) {
                float lo[8], hi[8];
#pragma unroll
                for (int t = 0; t < 8; ++t) {
                    float2 u = unpack2(hacc[jp][t]);
                    lo[t] = silu_f(u.x); hi[t] = silu_f(u.y);
                }
                float* r0 = &hs[(j0 + 2 * jp + 0) * HS_STR + t0];
                float* r1 = &hs[(j0 + 2 * jp + 1) * HS_STR + t0];
                *reinterpret_cast<float4*>(r0)     = make_float4(lo[0], lo[1], lo[2], lo[3]);
                *reinterpret_cast<float4*>(r0 + 4) = make_float4(lo[4], lo[5], lo[6], lo[7]);
                *reinterpret_cast<float4*>(r1)     = make_float4(hi[0], hi[1], hi[2], hi[3]);
                *reinterpret_cast<float4*>(r1 + 4) = make_float4(hi[4], hi[5], hi[6], hi[7]);
            }
        }
        __syncthreads();

        // ---- GEMM2: lane group covers e (coalesced STG); 8 tokens/thread ----
        {
            const int e0 = (tid & 7) * 4;
            const int t0 = (tid >> 3) * 8;
            u64 oacc[2][8];
            u64 bp0 = *reinterpret_cast<const u64*>(&b2s[e0]);
            u64 bp1 = *reinterpret_cast<const u64*>(&b2s[e0 + 2]);
#pragma unroll
            for (int t = 0; t < 8; ++t) { oacc[0][t] = bp0; oacc[1][t] = bp1; }
#pragma unroll 4
            for (int j = 0; j < H_; ++j) {
                const float* hr = &hs[j * HS_STR + t0];
                float4 ha = *reinterpret_cast<const float4*>(hr);
                float4 hb = *reinterpret_cast<const float4*>(hr + 4);
                u64 hq[8] = {pack2(ha.x, ha.x), pack2(ha.y, ha.y),
                             pack2(ha.z, ha.z), pack2(ha.w, ha.w),
                             pack2(hb.x, hb.x), pack2(hb.y, hb.y),
                             pack2(hb.z, hb.z), pack2(hb.w, hb.w)};
                ulonglong2 w = *reinterpret_cast<const ulonglong2*>(&W2t[j * E_ + e0]);
#pragma unroll
                for (int t = 0; t < 8; ++t) {
                    oacc[0][t] = ffma2(w.x, hq[t], oacc[0][t]);
                    oacc[1][t] = ffma2(w.y, hq[t], oacc[1][t]);
                }
            }
            float* ob = out + ((size_t)b * S_ + tileB * TB_TOK + t0) * E_ + e0;
#pragma unroll
            for (int t = 0; t < 8; ++t) {
                float2 u0 = unpack2(oacc[0][t]);
                float2 u1 = unpack2(oacc[1][t]);
                *reinterpret_cast<float4*>(ob + t * E_) =
                    make_float4(u0.x, u0.y, u1.x, u1.y);
            }
        }
        __syncthreads();
    }
}

extern "C" void kernel_launch(void* const* d_in, const int* in_sizes, int n_in,
                              void* d_out, int out_size) {
    const float* x  = (const float*)d_in[0];
    const float* Qw = (const float*)d_in[1];
    const float* W1 = (const float*)d_in[2];
    const float* b1 = (const float*)d_in[3];
    const float* W2 = (const float*)d_in[4];
    const float* b2 = (const float*)d_in[5];
    float* out = (float*)d_out;

    const int smemB = SMB_FLOATS * sizeof(float);  // 83,456 B -> 2 blocks/SM
    cudaFuncSetAttribute(k_passB, cudaFuncAttributeMaxDynamicSharedMemorySize, smemB);

    k_passA<<<dim3(NBA_, B_), 256>>>(x, Qw);
    k_passB<<<dim3(TB_TILES / TPB_, B_), 256, smemB>>>(W1, b1, W2, b2, out);
}

// round 10
// speedup vs baseline: 1.0284x; 1.0284x over previous
#include <cuda_runtime.h>

#define B_ 64
#define S_ 8192
#define E_ 32
#define H_ 64
// ---- pass A tiling (R8, unchanged) ----
#define T_ 128
#define TILES_ (S_ / T_)       // 64
#define TPA_ 4
#define NBA_ (TILES_ / TPA_)   // 16
#define XP_ 132
// ---- pass B (tensor) ----
#define PB_TPB 4               // tiles per block -> grid (16, 64)
#define W_STR 68               // weight row stride (conflict-free frag loads)
#define Q_STR 132              // qs row stride
#define HS_STR 68              // hs row stride
// dynamic smem float offsets
#define W1HI_OFF 0
#define W1LO_OFF (W1HI_OFF + E_ * W_STR)      // 2176
#define W2HI_OFF (W1LO_OFF + E_ * W_STR)
#define W2LO_OFF (W2HI_OFF + E_ * W_STR)
#define QS_OFF   (W2LO_OFF + E_ * W_STR)      // 8704
#define HS_OFF   (QS_OFF + E_ * Q_STR)        // 12928
#define B1_OFF   (HS_OFF + T_ * HS_STR)       // 21632
#define B2_OFF   (B1_OFF + H_)
#define RSQ_OFF  (B2_OFF + E_)
#define SMB_FLOATS (RSQ_OFF + E_)             // 21760 -> 87040 B

typedef unsigned long long u64;

// Scratch: q in [b][tile128][f][128] layout + per-block sumsq partials.
__device__ __align__(16) static float g_q[(size_t)B_ * S_ * E_];
__device__ static float g_part[B_ * NBA_ * E_];

__device__ __forceinline__ u64 pack2(float lo, float hi) {
    u64 r; asm("mov.b64 %0, {%1,%2};" : "=l"(r) : "f"(lo), "f"(hi)); return r;
}
__device__ __forceinline__ float2 unpack2(u64 v) {
    float2 f; asm("mov.b64 {%0,%1}, %2;" : "=f"(f.x), "=f"(f.y) : "l"(v)); return f;
}
__device__ __forceinline__ u64 ffma2(u64 a, u64 b, u64 c) {
    u64 d; asm("fma.rn.f32x2 %0, %1, %2, %3;" : "=l"(d) : "l"(a), "l"(b), "l"(c));
    return d;
}
__device__ __forceinline__ float silu_f(float v) {
    return v * __fdividef(1.0f, 1.0f + __expf(-v));  // ~1e-7 rel err; budget 1e-3
}
__device__ __forceinline__ unsigned tf32r(float v) {
    unsigned r; asm("cvt.rna.tf32.f32 %0, %1;" : "=r"(r) : "f"(v)); return r;
}
__device__ __forceinline__ void mma_tf32(float& d0, float& d1, float& d2, float& d3,
                                         unsigned a0, unsigned a1, unsigned a2, unsigned a3,
                                         unsigned b0, unsigned b1) {
    asm("mma.sync.aligned.m16n8k8.row.col.f32.tf32.tf32.f32 "
        "{%0,%1,%2,%3},{%4,%5,%6,%7},{%8,%9},{%0,%1,%2,%3};"
        : "+f"(d0), "+f"(d1), "+f"(d2), "+f"(d3)
        : "r"(a0), "r"(a1), "r"(a2), "r"(a3), "r"(b0), "r"(b1));
}
// 3-term split product accumulate: D += A*B with A,B split hi/lo (lo*lo dropped)
__device__ __forceinline__ void mma_x3(float* d,
                                       const unsigned* ah, const unsigned* al,
                                       unsigned bh0, unsigned bh1,
                                       unsigned bl0, unsigned bl1) {
    mma_tf32(d[0], d[1], d[2], d[3], ah[0], ah[1], ah[2], ah[3], bh0, bh1);
    mma_tf32(d[0], d[1], d[2], d[3], ah[0], ah[1], ah[2], ah[3], bl0, bl1);
    mma_tf32(d[0], d[1], d[2], d[3], al[0], al[1], al[2], al[3], bh0, bh1);
}

// ---------------- Pass A: q = silu(x @ Qw^T); per-block sumsq partials (R8) -----------
__global__ __launch_bounds__(256) void k_passA(const float* __restrict__ x,
                                               const float* __restrict__ Qw) {
    const int b = blockIdx.y, bx = blockIdx.x;
    const int tid = threadIdx.x, lane = tid & 31, wy = tid >> 5;
    __shared__ __align__(16) float Qt[E_ * E_];   // [e][f]
    __shared__ __align__(16) float xs[E_ * XP_];  // [e][t], padded

    {   // conflict-free transposed fill: lane carries f
        int f = tid & 31, eg = tid >> 5;
        for (int e = eg; e < E_; e += 8) Qt[e * E_ + f] = Qw[f * E_ + e];
    }

    const int t0 = lane * 4, f0 = wy * 4;
    float ss[4] = {0.f, 0.f, 0.f, 0.f};

    for (int tt = 0; tt < TPA_; ++tt) {
        const int tile = bx * TPA_ + tt;
        __syncthreads();
        const float4* xg = reinterpret_cast<const float4*>(
            x + ((size_t)b * S_ + tile * T_) * E_);
        for (int i = tid; i < T_ * E_ / 4; i += 256) {
            float4 v = xg[i];
            int t = i >> 3, e = (i & 7) * 4;
            xs[(e + 0) * XP_ + t] = v.x;
            xs[(e + 1) * XP_ + t] = v.y;
            xs[(e + 2) * XP_ + t] = v.z;
            xs[(e + 3) * XP_ + t] = v.w;
        }
        __syncthreads();

        u64 acc[2][4];
#pragma unroll
        for (int fp = 0; fp < 2; ++fp)
#pragma unroll
            for (int t = 0; t < 4; ++t) acc[fp][t] = 0ull;

#pragma unroll
        for (int e = 0; e < E_; ++e) {
            float4 q = *reinterpret_cast<const float4*>(&xs[e * XP_ + t0]);
            u64 qb0 = pack2(q.x, q.x), qb1 = pack2(q.y, q.y);
            u64 qb2 = pack2(q.z, q.z), qb3 = pack2(q.w, q.w);
            ulonglong2 w = *reinterpret_cast<const ulonglong2*>(&Qt[e * E_ + f0]);
            acc[0][0] = ffma2(w.x, qb0, acc[0][0]);
            acc[0][1] = ffma2(w.x, qb1, acc[0][1]);
            acc[0][2] = ffma2(w.x, qb2, acc[0][2]);
            acc[0][3] = ffma2(w.x, qb3, acc[0][3]);
            acc[1][0] = ffma2(w.y, qb0, acc[1][0]);
            acc[1][1] = ffma2(w.y, qb1, acc[1][1]);
            acc[1][2] = ffma2(w.y, qb2, acc[1][2]);
            acc[1][3] = ffma2(w.y, qb3, acc[1][3]);
        }

        float* qb = g_q + (((size_t)b * TILES_ + tile) * E_ + f0) * T_ + t0;
#pragma unroll
        for (int fp = 0; fp < 2; ++fp) {
            float2 a0 = unpack2(acc[fp][0]), a1 = unpack2(acc[fp][1]);
            float2 a2 = unpack2(acc[fp][2]), a3 = unpack2(acc[fp][3]);
            float l0 = silu_f(a0.x), l1 = silu_f(a1.x), l2 = silu_f(a2.x), l3 = silu_f(a3.x);
            float h0 = silu_f(a0.y), h1 = silu_f(a1.y), h2 = silu_f(a2.y), h3 = silu_f(a3.y);
            *reinterpret_cast<float4*>(qb + (2 * fp + 0) * T_) = make_float4(l0, l1, l2, l3);
            *reinterpret_cast<float4*>(qb + (2 * fp + 1) * T_) = make_float4(h0, h1, h2, h3);
            ss[2 * fp + 0] += l0 * l0 + l1 * l1 + l2 * l2 + l3 * l3;
            ss[2 * fp + 1] += h0 * h0 + h1 * h1 + h2 * h2 + h3 * h3;
        }
    }

#pragma unroll
    for (int i = 0; i < 4; ++i) {
#pragma unroll
        for (int o = 16; o > 0; o >>= 1) ss[i] += __shfl_xor_sync(0xffffffffu, ss[i], o);
    }
    if (lane == 0) {
#pragma unroll
        for (int i = 0; i < 4; ++i) g_part[(b * NBA_ + bx) * E_ + f0 + i] = ss[i];
    }
}

// ---------------- Pass B: tf32 tensor-core MLP (3-mma split) ----------------
__global__ __launch_bounds__(256) void k_passB(const float* __restrict__ W1,
                                               const float* __restrict__ b1,
                                               const float* __restrict__ W2,
                                               const float* __restrict__ b2,
                                               float* __restrict__ out) {
    extern __shared__ __align__(16) float sm[];
    float* W1hi = sm + W1HI_OFF;  // [e][j] * rsq[e], tf32-hi
    float* W1lo = sm + W1LO_OFF;
    float* W2hi = sm + W2HI_OFF;  // [e][j] (natural layout)
    float* W2lo = sm + W2LO_OFF;
    float* qs   = sm + QS_OFF;    // [e][Q_STR]
    float* hs   = sm + HS_OFF;    // [t][HS_STR]
    float* b1s  = sm + B1_OFF;
    float* b2s  = sm + B2_OFF;
    float* rsq  = sm + RSQ_OFF;

    const int b = blockIdx.y, bx = blockIdx.x, tid = threadIdx.x;
    const int lane = tid & 31, w = tid >> 5;
    const int g = lane >> 2, c = lane & 3;
    const int t0 = w * 16;  // warp's m16 token slice within the tile

    if (tid < E_) {
        float s = 0.f;
#pragma unroll
        for (int k = 0; k < NBA_; ++k) s += g_part[(b * NBA_ + k) * E_ + tid];
        rsq[tid] = 1.0f / fmaxf(sqrtf(s), 1e-12f);
        b2s[tid] = b2[b * E_ + tid];
    }
    if (tid < H_) b1s[tid] = b1[b * H_ + tid];
    __syncthreads();

    const size_t wbase = (size_t)b * H_ * E_;
    {   // W1 [j][e] -> [e][j]*rsq, split hi/lo (lane carries j: conflict-free STS)
        int j = tid & 63, eg = tid >> 6;
        for (int e = eg; e < E_; e += 4) {
            float v = W1[wbase + j * E_ + e] * rsq[e];
            unsigned h = tf32r(v);
            W1hi[e * W_STR + j] = __uint_as_float(h);
            W1lo[e * W_STR + j] = __uint_as_float(tf32r(v - __uint_as_float(h)));
        }
    }
    for (int i = tid; i < E_ * H_; i += 256) {  // W2 straight copy + split
        int e = i >> 6, j = i & 63;
        float v = W2[wbase + i];
        unsigned h = tf32r(v);
        W2hi[e * W_STR + j] = __uint_as_float(h);
        W2lo[e * W_STR + j] = __uint_as_float(tf32r(v - __uint_as_float(h)));
    }

    for (int tt = 0; tt < PB_TPB; ++tt) {
        const int tile = bx * PB_TPB + tt;
        __syncthreads();  // prior-iter GEMM1 readers of qs done (covers fills on tt=0)
        const float4* qg = reinterpret_cast<const float4*>(
            g_q + ((size_t)b * TILES_ + tile) * E_ * T_);
        for (int i = tid; i < E_ * T_ / 4; i += 256) {
            int e = i >> 5, q4 = (i & 31) * 4;
            *reinterpret_cast<float4*>(&qs[e * Q_STR + q4]) = qg[i];
        }
        __syncthreads();

        // ---- GEMM1: h[t][j] = silu(q @ W1n + b1), M=16/warp, N=64, K=32 ----
        {
            float acc[8][4];
#pragma unroll
            for (int jn = 0; jn < 8; ++jn) {
                float blo = b1s[8 * jn + 2 * c], bhi = b1s[8 * jn + 2 * c + 1];
                acc[jn][0] = blo; acc[jn][1] = bhi;
                acc[jn][2] = blo; acc[jn][3] = bhi;
            }
#pragma unroll
            for (int kc = 0; kc < 4; ++kc) {
                const int k0 = kc * 8;
                float av[4] = {qs[(k0 + c) * Q_STR + t0 + g],
                               qs[(k0 + c) * Q_STR + t0 + g + 8],
                               qs[(k0 + c + 4) * Q_STR + t0 + g],
                               qs[(k0 + c + 4) * Q_STR + t0 + g + 8]};
                unsigned ah[4], al[4];
#pragma unroll
                for (int i = 0; i < 4; ++i) {
                    ah[i] = tf32r(av[i]);
                    al[i] = tf32r(av[i] - __uint_as_float(ah[i]));
                }
#pragma unroll
                for (int jn = 0; jn < 8; ++jn) {
                    const int j0 = jn * 8;
                    unsigned bh0 = __float_as_uint(W1hi[(k0 + c) * W_STR + j0 + g]);
                    unsigned bh1 = __float_as_uint(W1hi[(k0 + c + 4) * W_STR + j0 + g]);
                    unsigned bl0 = __float_as_uint(W1lo[(k0 + c) * W_STR + j0 + g]);
                    unsigned bl1 = __float_as_uint(W1lo[(k0 + c + 4) * W_STR + j0 + g]);
                    mma_x3(acc[jn], ah, al, bh0, bh1, bl0, bl1);
                }
            }
#pragma unroll
            for (int jn = 0; jn < 8; ++jn) {  // silu + scatter to hs[t][j]
                const int j = jn * 8 + 2 * c;
                hs[(t0 + g) * HS_STR + j]         = silu_f(acc[jn][0]);
                hs[(t0 + g) * HS_STR + j + 1]     = silu_f(acc[jn][1]);
                hs[(t0 + g + 8) * HS_STR + j]     = silu_f(acc[jn][2]);
                hs[(t0 + g + 8) * HS_STR + j + 1] = silu_f(acc[jn][3]);
            }
        }
        __syncthreads();

        // ---- GEMM2: out[t][e] = h @ W2n + b2, M=16/warp, N=32, K=64 ----
        {
            float oacc[4][4];
#pragma unroll
            for (int en = 0; en < 4; ++en) {
                float blo = b2s[8 * en + 2 * c], bhi = b2s[8 * en + 2 * c + 1];
                oacc[en][0] = blo; oacc[en][1] = bhi;
                oacc[en][2] = blo; oacc[en][3] = bhi;
            }
#pragma unroll
            for (int kc = 0; kc < 8; ++kc) {
                const int k0 = kc * 8;
                float av[4] = {hs[(t0 + g) * HS_STR + k0 + c],
                               hs[(t0 + g + 8) * HS_STR + k0 + c],
                               hs[(t0 + g) * HS_STR + k0 + c + 4],
                               hs[(t0 + g + 8) * HS_STR + k0 + c + 4]};
                unsigned ah[4], al[4];
#pragma unroll
                for (int i = 0; i < 4; ++i) {
                    ah[i] = tf32r(av[i]);
                    al[i] = tf32r(av[i] - __uint_as_float(ah[i]));
                }
#pragma unroll
                for (int en = 0; en < 4; ++en) {
                    const int e0 = en * 8;
                    unsigned bh0 = __float_as_uint(W2hi[(e0 + g) * W_STR + k0 + c]);
                    unsigned bh1 = __float_as_uint(W2hi[(e0 + g) * W_STR + k0 + c + 4]);
                    unsigned bl0 = __float_as_uint(W2lo[(e0 + g) * W_STR + k0 + c]);
                    unsigned bl1 = __float_as_uint(W2lo[(e0 + g) * W_STR + k0 + c + 4]);
                    mma_x3(oacc[en], ah, al, bh0, bh1, bl0, bl1);
                }
            }
            float* ob = out + ((size_t)b * S_ + tile * T_ + t0) * E_;
#pragma unroll
            for (int en = 0; en < 4; ++en) {
                const int e = en * 8 + 2 * c;
                *reinterpret_cast<float2*>(ob + (g)     * E_ + e) =
                    make_float2(oacc[en][0], oacc[en][1]);
                *reinterpret_cast<float2*>(ob + (g + 8) * E_ + e) =
                    make_float2(oacc[en][2], oacc[en][3]);
            }
        }
    }
}

extern "C" void kernel_launch(void* const* d_in, const int* in_sizes, int n_in,
                              void* d_out, int out_size) {
    const float* x  = (const float*)d_in[0];
    const float* Qw = (const float*)d_in[1];
    const float* W1 = (const float*)d_in[2];
    const float* b1 = (const float*)d_in[3];
    const float* W2 = (const float*)d_in[4];
    const float* b2 = (const float*)d_in[5];
    float* out = (float*)d_out;

    const int smemB = SMB_FLOATS * sizeof(float);  // 87,040 B -> 2 blocks/SM
    cudaFuncSetAttribute(k_passB, cudaFuncAttributeMaxDynamicSharedMemorySize, smemB);

    k_passA<<<dim3(NBA_, B_), 256>>>(x, Qw);
    k_passB<<<dim3(TILES_ / PB_TPB, B_), 256, smemB>>>(W1, b1, W2, b2, out);
}

// round 11
// speedup vs baseline: 1.4620x; 1.4216x over previous
#include <cuda_runtime.h>

#define B_ 64
#define S_ 8192
#define E_ 32
#define H_ 64
#define PT_ 128                 // tokens per tile
#define PTILES_ (S_ / PT_)      // 64
#define TPA_ 4                  // tiles per pass-A block
#define NBA_ (PTILES_ / TPA_)   // 16
#define TPB_ 4                  // tiles per pass-B block
#define NBB_ (PTILES_ / TPB_)   // 16

// strides in 4-byte units (all chosen for conflict-free fragment access)
#define QT_STR 40   // Qt tf32 [e=32][f=32] floats      bank = 8c+g
#define W1_STR 20   // W1bf [j=64][epair=16] u32        bank = 4g+c
#define W2_STR 36   // W2bf [e=32][jpair=32] u32        bank = 4g+c
#define QS_STR 20   // qs   [t=128][epair=16] u32       bank = 4g+c
#define HS_STR 36   // hs   [t=128][jpair=32] u32       bank = 4g+c
// pass-B dynamic smem offsets (4B units)
#define QTH_OFF 0
#define QTL_OFF (QTH_OFF + E_ * QT_STR)     // 1280
#define W1H_OFF (QTL_OFF + E_ * QT_STR)     // 2560
#define W1L_OFF (W1H_OFF + H_ * W1_STR)     // 3840
#define W2H_OFF (W1L_OFF + H_ * W1_STR)     // 5120
#define W2L_OFF (W2H_OFF + E_ * W2_STR)     // 6272
#define QSH_OFF (W2L_OFF + E_ * W2_STR)     // 7424
#define QSL_OFF (QSH_OFF + PT_ * QS_STR)    // 9984
#define HSH_OFF (QSL_OFF + PT_ * QS_STR)    // 12544
#define HSL_OFF (HSH_OFF + PT_ * HS_STR)    // 17152
#define B1S_OFF (HSL_OFF + PT_ * HS_STR)    // 21760
#define B2S_OFF (B1S_OFF + H_)
#define RSQ_OFF (B2S_OFF + E_)
#define SMB_FLOATS (RSQ_OFF + E_)           // 21888 -> 87552 B

// Per-block sumsq partials (the only scratch left; no g_q).
__device__ static float g_part[B_ * NBA_ * E_];

__device__ __forceinline__ float silu_f(float v) {
    return v * __fdividef(1.0f, 1.0f + __expf(-v));  // ~1e-7 rel; budget 1e-3
}
__device__ __forceinline__ unsigned tf32r(float v) {
    unsigned r; asm("cvt.rna.tf32.f32 %0, %1;" : "=r"(r) : "f"(v)); return r;
}
__device__ __forceinline__ void mma_tf32(float* d, const unsigned* a,
                                         unsigned b0, unsigned b1) {
    asm("mma.sync.aligned.m16n8k8.row.col.f32.tf32.tf32.f32 "
        "{%0,%1,%2,%3},{%4,%5,%6,%7},{%8,%9},{%0,%1,%2,%3};"
        : "+f"(d[0]), "+f"(d[1]), "+f"(d[2]), "+f"(d[3])
        : "r"(a[0]), "r"(a[1]), "r"(a[2]), "r"(a[3]), "r"(b0), "r"(b1));
}
__device__ __forceinline__ void mma_bf16(float* d, const unsigned* a,
                                         unsigned b0, unsigned b1) {
    asm("mma.sync.aligned.m16n8k16.row.col.f32.bf16.bf16.f32 "
        "{%0,%1,%2,%3},{%4,%5,%6,%7},{%8,%9},{%0,%1,%2,%3};"
        : "+f"(d[0]), "+f"(d[1]), "+f"(d[2]), "+f"(d[3])
        : "r"(a[0]), "r"(a[1]), "r"(a[2]), "r"(a[3]), "r"(b0), "r"(b1));
}
__device__ __forceinline__ void mma_bf3(float* d, const unsigned* ah, const unsigned* al,
                                        unsigned bh0, unsigned bh1,
                                        unsigned bl0, unsigned bl1) {
    mma_bf16(d, ah, bh0, bh1);
    mma_bf16(d, ah, bl0, bl1);
    mma_bf16(d, al, bh0, bh1);
}
// pack two floats as bf16x2: element k -> low half, k+1 -> high half
__device__ __forceinline__ unsigned bf2pack(float lo, float hi) {
    unsigned r; asm("cvt.rn.bf16x2.f32 %0, %1, %2;" : "=r"(r) : "f"(hi), "f"(lo));
    return r;
}
__device__ __forceinline__ void bfsplit(float v0, float v1, unsigned& hi, unsigned& lo) {
    hi = bf2pack(v0, v1);
    float h0 = __uint_as_float(hi << 16);
    float h1 = __uint_as_float(hi & 0xFFFF0000u);
    lo = bf2pack(v0 - h0, v1 - h1);
}

// ---------------- Pass A: sumsq of silu(x @ Qw^T) only (no q store) ----------------
__global__ __launch_bounds__(256) void k_passA(const float* __restrict__ x,
                                               const float* __restrict__ Qw) {
    __shared__ __align__(16) float QtH[E_ * QT_STR], QtL[E_ * QT_STR];
    __shared__ float ssA[8][E_];
    const int b = blockIdx.y, bx = blockIdx.x, tid = threadIdx.x;
    const int lane = tid & 31, w = tid >> 5;
    const int g = lane >> 2, c = lane & 3;
    const int t0 = w * 16;

    for (int i = tid; i < E_ * E_; i += 256) {  // Qw[f][e] -> Qt[e][f] hi/lo
        int f = i >> 5, e = i & 31;
        float v = Qw[i];
        unsigned h = tf32r(v);
        QtH[e * QT_STR + f] = __uint_as_float(h);
        QtL[e * QT_STR + f] = __uint_as_float(tf32r(v - __uint_as_float(h)));
    }
    __syncthreads();

    float ss[4][2];
#pragma unroll
    for (int fn = 0; fn < 4; ++fn) ss[fn][0] = ss[fn][1] = 0.f;

    for (int tt = 0; tt < TPA_; ++tt) {
        const int tile = bx * TPA_ + tt;
        const float* xw = x + ((size_t)b * S_ + tile * PT_ + t0) * E_;
        float qa[4][4];
#pragma unroll
        for (int fn = 0; fn < 4; ++fn)
#pragma unroll
            for (int i = 0; i < 4; ++i) qa[fn][i] = 0.f;

#pragma unroll
        for (int kc = 0; kc < 4; ++kc) {
            const int k0 = kc * 8;
            float av[4] = {xw[g * E_ + k0 + c],       xw[(g + 8) * E_ + k0 + c],
                           xw[g * E_ + k0 + c + 4],   xw[(g + 8) * E_ + k0 + c + 4]};
            unsigned ah[4], al[4];
#pragma unroll
            for (int i = 0; i < 4; ++i) {
                ah[i] = tf32r(av[i]);
                al[i] = tf32r(av[i] - __uint_as_float(ah[i]));
            }
#pragma unroll
            for (int fn = 0; fn < 4; ++fn) {
                const int f0 = fn * 8;
                unsigned bh0 = __float_as_uint(QtH[(k0 + c) * QT_STR + f0 + g]);
                unsigned bh1 = __float_as_uint(QtH[(k0 + c + 4) * QT_STR + f0 + g]);
                unsigned bl0 = __float_as_uint(QtL[(k0 + c) * QT_STR + f0 + g]);
                unsigned bl1 = __float_as_uint(QtL[(k0 + c + 4) * QT_STR + f0 + g]);
                mma_tf32(qa[fn], ah, bh0, bh1);
                mma_tf32(qa[fn], ah, bl0, bl1);
                mma_tf32(qa[fn], al, bh0, bh1);
            }
        }
#pragma unroll
        for (int fn = 0; fn < 4; ++fn) {
            float s0 = silu_f(qa[fn][0]), s1 = silu_f(qa[fn][1]);
            float s2 = silu_f(qa[fn][2]), s3 = silu_f(qa[fn][3]);
            ss[fn][0] += s0 * s0 + s2 * s2;
            ss[fn][1] += s1 * s1 + s3 * s3;
        }
    }

    // reduce over g (lane bits 2..4), then over warps
#pragma unroll
    for (int m = 4; m <= 16; m <<= 1)
#pragma unroll
        for (int fn = 0; fn < 4; ++fn) {
            ss[fn][0] += __shfl_xor_sync(0xffffffffu, ss[fn][0], m);
            ss[fn][1] += __shfl_xor_sync(0xffffffffu, ss[fn][1], m);
        }
    if (lane < 4) {
#pragma unroll
        for (int fn = 0; fn < 4; ++fn) {
            ssA[w][fn * 8 + 2 * lane]     = ss[fn][0];
            ssA[w][fn * 8 + 2 * lane + 1] = ss[fn][1];
        }
    }
    __syncthreads();
    if (tid < E_) {
        float s = 0.f;
#pragma unroll
        for (int k = 0; k < 8; ++k) s += ssA[k][tid];
        g_part[(b * NBA_ + bx) * E_ + tid] = s;
    }
}

// ---------------- Pass B: fused q-recompute + MLP, sync-free tile loop ----------------
__global__ __launch_bounds__(256) void k_passB(const float* __restrict__ x,
                                               const float* __restrict__ Qw,
                                               const float* __restrict__ W1,
                                               const float* __restrict__ b1,
                                               const float* __restrict__ W2,
                                               const float* __restrict__ b2,
                                               float* __restrict__ out) {
    extern __shared__ __align__(16) float sm[];
    float*    QtH = sm + QTH_OFF;
    float*    QtL = sm + QTL_OFF;
    unsigned* w1h = reinterpret_cast<unsigned*>(sm + W1H_OFF);
    unsigned* w1l = reinterpret_cast<unsigned*>(sm + W1L_OFF);
    unsigned* w2h = reinterpret_cast<unsigned*>(sm + W2H_OFF);
    unsigned* w2l = reinterpret_cast<unsigned*>(sm + W2L_OFF);
    unsigned* qsh = reinterpret_cast<unsigned*>(sm + QSH_OFF);
    unsigned* qsl = reinterpret_cast<unsigned*>(sm + QSL_OFF);
    unsigned* hsh = reinterpret_cast<unsigned*>(sm + HSH_OFF);
    unsigned* hsl = reinterpret_cast<unsigned*>(sm + HSL_OFF);
    float* b1s = sm + B1S_OFF;
    float* b2s = sm + B2S_OFF;
    float* rsq = sm + RSQ_OFF;

    const int b = blockIdx.y, bx = blockIdx.x, tid = threadIdx.x;
    const int lane = tid & 31, w = tid >> 5;
    const int g = lane >> 2, c = lane & 3;
    const int t0 = w * 16;

    if (tid < E_) {
        float s = 0.f;
#pragma unroll
        for (int k = 0; k < NBA_; ++k) s += g_part[(b * NBA_ + k) * E_ + tid];
        rsq[tid] = 1.0f / fmaxf(sqrtf(s), 1e-12f);
        b2s[tid] = b2[b * E_ + tid];
    }
    if (tid < H_) b1s[tid] = b1[b * H_ + tid];
    __syncthreads();

    for (int i = tid; i < E_ * E_; i += 256) {  // Qt hi/lo
        int f = i >> 5, e = i & 31;
        float v = Qw[i];
        unsigned h = tf32r(v);
        QtH[e * QT_STR + f] = __uint_as_float(h);
        QtL[e * QT_STR + f] = __uint_as_float(tf32r(v - __uint_as_float(h)));
    }
    const size_t wbase = (size_t)b * H_ * E_;
    for (int i = tid; i < H_ * (E_ / 2); i += 256) {  // W1bf[j][epair], rsq folded
        int j = i >> 4, ep = i & 15;
        float2 v = *reinterpret_cast<const float2*>(W1 + wbase + j * E_ + 2 * ep);
        unsigned hi, lo;
        bfsplit(v.x * rsq[2 * ep], v.y * rsq[2 * ep + 1], hi, lo);
        w1h[j * W1_STR + ep] = hi;
        w1l[j * W1_STR + ep] = lo;
    }
    for (int i = tid; i < E_ * (H_ / 2); i += 256) {  // W2bf[e][jpair]
        int e = i >> 5, jp = i & 31;
        float2 v = *reinterpret_cast<const float2*>(W2 + wbase + e * H_ + 2 * jp);
        unsigned hi, lo;
        bfsplit(v.x, v.y, hi, lo);
        w2h[e * W2_STR + jp] = hi;
        w2l[e * W2_STR + jp] = lo;
    }
    __syncthreads();

    // Tile loop: each warp owns tokens [t0, t0+16) — fully warp-local, no syncs.
    for (int tt = 0; tt < TPB_; ++tt) {
        const int tile = bx * TPB_ + tt;
        const float* xw = x + ((size_t)b * S_ + tile * PT_ + t0) * E_;

        // ---- Q-GEMM (tf32 3-term): q = x @ Qt ----
        float qa[4][4];
#pragma unroll
        for (int fn = 0; fn < 4; ++fn)
#pragma unroll
            for (int i = 0; i < 4; ++i) qa[fn][i] = 0.f;
#pragma unroll
        for (int kc = 0; kc < 4; ++kc) {
            const int k0 = kc * 8;
            float av[4] = {xw[g * E_ + k0 + c],       xw[(g + 8) * E_ + k0 + c],
                           xw[g * E_ + k0 + c + 4],   xw[(g + 8) * E_ + k0 + c + 4]};
            unsigned ah[4], al[4];
#pragma unroll
            for (int i = 0; i < 4; ++i) {
                ah[i] = tf32r(av[i]);
                al[i] = tf32r(av[i] - __uint_as_float(ah[i]));
            }
#pragma unroll
            for (int fn = 0; fn < 4; ++fn) {
                const int f0 = fn * 8;
                unsigned bh0 = __float_as_uint(QtH[(k0 + c) * QT_STR + f0 + g]);
                unsigned bh1 = __float_as_uint(QtH[(k0 + c + 4) * QT_STR + f0 + g]);
                unsigned bl0 = __float_as_uint(QtL[(k0 + c) * QT_STR + f0 + g]);
                unsigned bl1 = __float_as_uint(QtL[(k0 + c + 4) * QT_STR + f0 + g]);
                mma_tf32(qa[fn], ah, bh0, bh1);
                mma_tf32(qa[fn], ah, bl0, bl1);
                mma_tf32(qa[fn], al, bh0, bh1);
            }
        }
        // silu + bf16-split pack into qs (warp-local rows)
#pragma unroll
        for (int fn = 0; fn < 4; ++fn) {
            const int col = fn * 4 + c;
            unsigned hi, lo;
            bfsplit(silu_f(qa[fn][0]), silu_f(qa[fn][1]), hi, lo);
            qsh[(t0 + g) * QS_STR + col] = hi;
            qsl[(t0 + g) * QS_STR + col] = lo;
            bfsplit(silu_f(qa[fn][2]), silu_f(qa[fn][3]), hi, lo);
            qsh[(t0 + g + 8) * QS_STR + col] = hi;
            qsl[(t0 + g + 8) * QS_STR + col] = lo;
        }
        __syncwarp();

        // ---- GEMM1 (bf16 3-term): h = silu(q̂ @ W1n + b1), N=64, K=32 ----
        float ha[8][4];
#pragma unroll
        for (int jn = 0; jn < 8; ++jn) {
            float blo = b1s[jn * 8 + 2 * c], bhi = b1s[jn * 8 + 2 * c + 1];
            ha[jn][0] = blo; ha[jn][1] = bhi; ha[jn][2] = blo; ha[jn][3] = bhi;
        }
#pragma unroll
        for (int kc = 0; kc < 2; ++kc) {
            const int k8 = kc * 8;
            unsigned ah[4] = {qsh[(t0 + g) * QS_STR + k8 + c],
                              qsh[(t0 + g + 8) * QS_STR + k8 + c],
                              qsh[(t0 + g) * QS_STR + k8 + c + 4],
                              qsh[(t0 + g + 8) * QS_STR + k8 + c + 4]};
            unsigned al[4] = {qsl[(t0 + g) * QS_STR + k8 + c],
                              qsl[(t0 + g + 8) * QS_STR + k8 + c],
                              qsl[(t0 + g) * QS_STR + k8 + c + 4],
                              qsl[(t0 + g + 8) * QS_STR + k8 + c + 4]};
#pragma unroll
            for (int jn = 0; jn < 8; ++jn) {
                const int jr = jn * 8 + g;
                mma_bf3(ha[jn], ah, al,
                        w1h[jr * W1_STR + k8 + c], w1h[jr * W1_STR + k8 + c + 4],
                        w1l[jr * W1_STR + k8 + c], w1l[jr * W1_STR + k8 + c + 4]);
            }
        }
        // silu + pack into hs (warp-local rows)
#pragma unroll
        for (int jn = 0; jn < 8; ++jn) {
            const int col = jn * 4 + c;
            unsigned hi, lo;
            bfsplit(silu_f(ha[jn][0]), silu_f(ha[jn][1]), hi, lo);
            hsh[(t0 + g) * HS_STR + col] = hi;
            hsl[(t0 + g) * HS_STR + col] = lo;
            bfsplit(silu_f(ha[jn][2]), silu_f(ha[jn][3]), hi, lo);
            hsh[(t0 + g + 8) * HS_STR + col] = hi;
            hsl[(t0 + g + 8) * HS_STR + col] = lo;
        }
        __syncwarp();

        // ---- GEMM2 (bf16 3-term): out = h @ W2n + b2, N=32, K=64 ----
        float oa[4][4];
#pragma unroll
        for (int en = 0; en < 4; ++en) {
            float blo = b2s[en * 8 + 2 * c], bhi = b2s[en * 8 + 2 * c + 1];
            oa[en][0] = blo; oa[en][1] = bhi; oa[en][2] = blo; oa[en][3] = bhi;
        }
#pragma unroll
        for (int kc = 0; kc < 4; ++kc) {
            const int k8 = kc * 8;
            unsigned ah[4] = {hsh[(t0 + g) * HS_STR + k8 + c],
                              hsh[(t0 + g + 8) * HS_STR + k8 + c],
                              hsh[(t0 + g) * HS_STR + k8 + c + 4],
                              hsh[(t0 + g + 8) * HS_STR + k8 + c + 4]};
            unsigned al[4] = {hsl[(t0 + g) * HS_STR + k8 + c],
                              hsl[(t0 + g + 8) * HS_STR + k8 + c],
                              hsl[(t0 + g) * HS_STR + k8 + c + 4],
                              hsl[(t0 + g + 8) * HS_STR + k8 + c + 4]};
#pragma unroll
            for (int en = 0; en < 4; ++en) {
                const int er = en * 8 + g;
                mma_bf3(oa[en], ah, al,
                        w2h[er * W2_STR + k8 + c], w2h[er * W2_STR + k8 + c + 4],
                        w2l[er * W2_STR + k8 + c], w2l[er * W2_STR + k8 + c + 4]);
            }
        }
        float* ob = out + ((size_t)b * S_ + tile * PT_ + t0) * E_;
#pragma unroll
        for (int en = 0; en < 4; ++en) {
            const int e2 = en * 8 + 2 * c;
            *reinterpret_cast<float2*>(ob + g * E_ + e2) =
                make_float2(oa[en][0], oa[en][1]);
            *reinterpret_cast<float2*>(ob + (g + 8) * E_ + e2) =
                make_float2(oa[en][2], oa[en][3]);
        }
        __syncwarp();
    }
}

extern "C" void kernel_launch(void* const* d_in, const int* in_sizes, int n_in,
                              void* d_out, int out_size) {
    const float* x  = (const float*)d_in[0];
    const float* Qw = (const float*)d_in[1];
    const float* W1 = (const float*)d_in[2];
    const float* b1 = (const float*)d_in[3];
    const float* W2 = (const float*)d_in[4];
    const float* b2 = (const float*)d_in[5];
    float* out = (float*)d_out;

    const int smemB = SMB_FLOATS * sizeof(float);  // 87,552 B -> 2 blocks/SM
    cudaFuncSetAttribute(k_passB, cudaFuncAttributeMaxDynamicSharedMemorySize, smemB);

    k_passA<<<dim3(NBA_, B_), 256>>>(x, Qw);
    k_passB<<<dim3(NBB_, B_), 256, smemB>>>(x, Qw, W1, b1, W2, b2, out);
}